// round 14
// baseline (speedup 1.0000x reference)
#include <cuda_runtime.h>
#include <cuda_fp16.h>
#include <cuda_bf16.h>
#include <math.h>
#include <cstdint>

#define NN 50000
#define EE 800000
#define FIN 165
#define MPAD 50048            // 391 * 128

// ---------------- scratch (device globals; no allocation allowed) ----------------
__device__ uint16_t g_xH[MPAD * 176], g_xL[MPAD * 176];
__device__ uint16_t g_p1H[MPAD * 256], g_p1L[MPAD * 256];
__device__ uint16_t g_p2H[MPAD * 256], g_p2L[MPAD * 256];
__device__ uint16_t g_w1H[256 * 176], g_w1L[256 * 176];
__device__ uint16_t g_w2H[256 * 256], g_w2L[256 * 256];
__device__ uint16_t g_w3H[128 * 256], g_w3L[128 * 256];
__device__ uint16_t g_skH[128 * 176], g_skL[128 * 176];
__device__ uint32_t g_hh[NN * 128];     // packed half2 features
__device__ float g_xinit[NN * 128];
__device__ float g_asrc[NN * 8];
__device__ float g_adst[NN * 8];
__device__ int   g_rowptr[NN + 1];
__device__ int   g_cursor[NN];
__device__ int   g_col[EE];
__device__ int   g_bsum[256];

// ---------------- split helpers ----------------
__device__ __forceinline__ uint32_t split_pair(float v0, float v1, uint32_t& loOut) {
    uint32_t b0 = __float_as_uint(v0), b1 = __float_as_uint(v1);
    float l0 = v0 - __uint_as_float(b0 & 0xFFFF0000u);
    float l1 = v1 - __uint_as_float(b1 & 0xFFFF0000u);
    __nv_bfloat162 lp = __floats2bfloat162_rn(l0, l1);
    loOut = *(uint32_t*)&lp;
    return (b0 >> 16) | (b1 & 0xFFFF0000u);
}
__device__ __forceinline__ void rec_pair(uint32_t h, uint32_t lo, float& r0, float& r1) {
    float h0 = __uint_as_float(h << 16);
    float h1 = __uint_as_float(h & 0xFFFF0000u);
    __nv_bfloat162 lp = *(__nv_bfloat162*)&lo;
    float2 lf = __bfloat1622float2(lp);
    r0 = h0 + lf.x; r1 = h1 + lf.y;
}

// ---------------- prep: split x + split/transpose weights ----------------
__global__ void k_split_x(const float* __restrict__ x, int n) {
    int idx = blockIdx.x * 256 + threadIdx.x;
    int row = idx / 88, cp = idx - row * 88;
    if (row >= n) return;
    int c0 = cp * 2;
    float v0 = (c0 < FIN) ? x[(size_t)row * FIN + c0] : 0.f;
    float v1 = (c0 + 1 < FIN) ? x[(size_t)row * FIN + c0 + 1] : 0.f;
    uint32_t lo, hi = split_pair(v0, v1, lo);
    ((uint32_t*)g_xH)[(size_t)row * 88 + cp] = hi;
    ((uint32_t*)g_xL)[(size_t)row * 88 + cp] = lo;
}
__global__ void k_split_w(const float* __restrict__ W, int K, int N, int Kp,
                          uint16_t* __restrict__ oH, uint16_t* __restrict__ oL) {
    int kp2 = Kp >> 1;
    int idx = blockIdx.x * 256 + threadIdx.x;
    if (idx >= N * kp2) return;
    int row = idx / kp2, cp = idx - row * kp2;
    int k0 = cp * 2;
    float v0 = (k0 < K) ? W[(size_t)k0 * N + row] : 0.f;
    float v1 = (k0 + 1 < K) ? W[(size_t)(k0 + 1) * N + row] : 0.f;
    uint32_t lo, hi = split_pair(v0, v1, lo);
    ((uint32_t*)oH)[(size_t)row * kp2 + cp] = hi;
    ((uint32_t*)oL)[(size_t)row * kp2 + cp] = lo;
}

// ---------------- CSR build (by destination), hierarchical scan ----------------
__global__ void k_zero(int n) {
    int i = blockIdx.x * blockDim.x + threadIdx.x;
    if (i < n) g_cursor[i] = 0;
}
__global__ void k_count(const int* __restrict__ dst, int e) {
    int i = blockIdx.x * blockDim.x + threadIdx.x;
    if (i < e) atomicAdd(&g_cursor[dst[i]], 1);
}
__global__ void k_bsum(int n) {
    __shared__ int sh[256];
    int i = blockIdx.x * 256 + threadIdx.x;
    sh[threadIdx.x] = (i < n) ? g_cursor[i] : 0;
    __syncthreads();
#pragma unroll
    for (int off = 128; off; off >>= 1) {
        if (threadIdx.x < off) sh[threadIdx.x] += sh[threadIdx.x + off];
        __syncthreads();
    }
    if (threadIdx.x == 0) g_bsum[blockIdx.x] = sh[0];
}
__global__ void k_bscan(int nb, int n) {
    __shared__ int sh[256];
    int t = threadIdx.x;
    int v = (t < nb) ? g_bsum[t] : 0;
    sh[t] = v;
    __syncthreads();
#pragma unroll
    for (int off = 1; off < 256; off <<= 1) {
        int u = (t >= off) ? sh[t - off] : 0;
        __syncthreads();
        sh[t] += u;
        __syncthreads();
    }
    if (t < nb) g_bsum[t] = sh[t] - v;
    if (t == 255) g_rowptr[n] = sh[255];
}
__global__ void k_rowptr(int n) {
    __shared__ int sh[256];
    int t = threadIdx.x;
    int i = blockIdx.x * 256 + t;
    int c = (i < n) ? g_cursor[i] : 0;
    sh[t] = c;
    __syncthreads();
#pragma unroll
    for (int off = 1; off < 256; off <<= 1) {
        int u = (t >= off) ? sh[t - off] : 0;
        __syncthreads();
        sh[t] += u;
        __syncthreads();
    }
    if (i < n) {
        int p = g_bsum[blockIdx.x] + sh[t] - c;
        g_rowptr[i] = p;
        g_cursor[i] = p;
    }
}
__global__ void k_scatter(const int* __restrict__ src, const int* __restrict__ dst, int e) {
    int i = blockIdx.x * blockDim.x + threadIdx.x;
    if (i >= e) return;
    int pos = atomicAdd(&g_cursor[dst[i]], 1);
    g_col[pos] = src[i];
}

// ---------------- mma / ldmatrix helpers ----------------
__device__ __forceinline__ void mma16816(float* c, const uint32_t* a, const uint32_t* b) {
    asm volatile(
        "mma.sync.aligned.m16n8k16.row.col.f32.bf16.bf16.f32 "
        "{%0,%1,%2,%3}, {%4,%5,%6,%7}, {%8,%9}, {%0,%1,%2,%3};"
        : "+f"(c[0]), "+f"(c[1]), "+f"(c[2]), "+f"(c[3])
        : "r"(a[0]), "r"(a[1]), "r"(a[2]), "r"(a[3]), "r"(b[0]), "r"(b[1]));
}
__device__ __forceinline__ void ldsm4(uint32_t* r, uint32_t addr) {
    asm volatile("ldmatrix.sync.aligned.m8n8.x4.shared.b16 {%0,%1,%2,%3}, [%4];"
                 : "=r"(r[0]), "=r"(r[1]), "=r"(r[2]), "=r"(r[3]) : "r"(addr));
}
__device__ __forceinline__ uint32_t smem_u32(const void* p) {
    uint32_t a;
    asm("{ .reg .u64 t; cvta.to.shared.u64 t, %1; cvt.u32.u64 %0, t; }" : "=r"(a) : "l"(p));
    return a;
}

#define LDSB 24   // bf16 per smem row (48B stride: 16B-aligned, conflict-free)

// ================= plane-fed bf16x3 tensor GEMM, 128x128 block, BK=16 =====================
template <bool FUSE_SKIP>
__global__ void __launch_bounds__(256, 2)
k_pgemm(const uint16_t* __restrict__ AH, const uint16_t* __restrict__ AL, int Kp,
        const uint16_t* __restrict__ BH, const uint16_t* __restrict__ BL,
        const uint16_t* __restrict__ SH_, const uint16_t* __restrict__ SL_,
        float* __restrict__ Cskip, const float* __restrict__ skb,
        uint32_t* __restrict__ hh, int M, int N,
        const float* __restrict__ scale,
        float* __restrict__ asrc, float* __restrict__ adst,
        const float* __restrict__ a_s, const float* __restrict__ a_d, int H) {
    __shared__ __align__(16) uint16_t AsH[2][128][LDSB];
    __shared__ __align__(16) uint16_t AsL[2][128][LDSB];
    __shared__ __align__(16) uint16_t BsH[2][128][LDSB];
    __shared__ __align__(16) uint16_t BsL[2][128][LDSB];

    int tid = threadIdx.x;
    int wid = tid >> 5;
    int lane = tid & 31;
    int g = lane >> 2, tg = lane & 3;
    int warp_m = wid & 3;
    int warp_n = wid >> 2;
    int bm = blockIdx.y * 128;

    const bool isSkip = FUSE_SKIP && (blockIdx.x == 0);
    int bn = FUSE_SKIP ? ((int)blockIdx.x - 1) * 128 : (int)blockIdx.x * 128;
    const uint16_t* pBH = isSkip ? SH_ : BH;
    const uint16_t* pBL = isSkip ? SL_ : BL;

    int r2 = tid >> 1, hf = tid & 1;
    size_t aoff = (size_t)(bm + r2) * Kp + hf * 8;
    size_t boff = (size_t)((isSkip ? 0 : bn) + r2) * Kp + hf * 8;

    float acc[2][8][4];
#pragma unroll
    for (int mt = 0; mt < 2; mt++)
#pragma unroll
        for (int nt = 0; nt < 8; nt++)
#pragma unroll
            for (int q = 0; q < 4; q++) acc[mt][nt][q] = 0.f;

    int lr = lane & 7, sel = lane >> 3;
    uint32_t aRow = (uint32_t)(warp_m * 32 + lr + ((sel & 1) << 3));
    uint32_t aColB = (uint32_t)(((sel >> 1) << 3) * 2);
    uint32_t bRow = (uint32_t)(warp_n * 64 + lr + ((sel >> 1) << 3));
    uint32_t bColB = (uint32_t)(((sel & 1) << 3) * 2);

    uint32_t sAH = smem_u32(&AsH[0][0][0]);
    uint32_t sAL = smem_u32(&AsL[0][0][0]);
    uint32_t sBH = smem_u32(&BsH[0][0][0]);
    uint32_t sBL = smem_u32(&BsL[0][0][0]);
    const uint32_t BUF = 128 * LDSB * 2;

    uint4 avh, avl, bvh, bvl;
    int nk = Kp >> 4;

#define LOADG(k0)                                              \
    {                                                          \
        avh = *(const uint4*)(AH + aoff + (k0));               \
        avl = *(const uint4*)(AL + aoff + (k0));               \
        bvh = *(const uint4*)(pBH + boff + (k0));              \
        bvl = *(const uint4*)(pBL + boff + (k0));              \
    }
#define STORES(buf)                                            \
    {                                                          \
        *(uint4*)&AsH[buf][r2][hf * 8] = avh;                  \
        *(uint4*)&AsL[buf][r2][hf * 8] = avl;                  \
        *(uint4*)&BsH[buf][r2][hf * 8] = bvh;                  \
        *(uint4*)&BsL[buf][r2][hf * 8] = bvl;                  \
    }

    LOADG(0);
    STORES(0);
    __syncthreads();

    for (int t = 0; t < nk; t++) {
        int cur = t & 1;
        uint32_t base = cur * BUF;
        if (t + 1 < nk) LOADG((t + 1) << 4);

        uint32_t aH2[2][4], aL2[2][4];
#pragma unroll
        for (int mt = 0; mt < 2; mt++) {
            uint32_t off = (aRow + mt * 16) * (LDSB * 2) + aColB;
            ldsm4(aH2[mt], sAH + base + off);
            ldsm4(aL2[mt], sAL + base + off);
        }
#pragma unroll
        for (int ntp = 0; ntp < 4; ntp++) {
            uint32_t off = (bRow + ntp * 16) * (LDSB * 2) + bColB;
            uint32_t bh[4], bl[4];
            ldsm4(bh, sBH + base + off);
            ldsm4(bl, sBL + base + off);
#pragma unroll
            for (int mt = 0; mt < 2; mt++) {
                mma16816(acc[mt][2 * ntp],     aH2[mt], bh);
                mma16816(acc[mt][2 * ntp],     aH2[mt], bl);
                mma16816(acc[mt][2 * ntp],     aL2[mt], bh);
                mma16816(acc[mt][2 * ntp + 1], aH2[mt], bh + 2);
                mma16816(acc[mt][2 * ntp + 1], aH2[mt], bl + 2);
                mma16816(acc[mt][2 * ntp + 1], aL2[mt], bh + 2);
            }
        }
        if (t + 1 < nk) {
            STORES(cur ^ 1);
            __syncthreads();
        }
    }
#undef LOADG
#undef STORES

    // ---- epilogue ----
    float scl = scale ? *scale : 1.0f;
    int cb_local = warp_n * 64;
    int cbase = bn + cb_local;
    int halfN = N >> 1;
#pragma unroll
    for (int mt = 0; mt < 2; mt++) {
#pragma unroll
        for (int rh = 0; rh < 2; rh++) {
            int r = bm + warp_m * 32 + mt * 16 + rh * 8 + g;
            float v[8][2];
            float ds0 = 0.f, dd0 = 0.f, ds1 = 0.f, dd1 = 0.f;
#pragma unroll
            for (int nt = 0; nt < 8; nt++) {
                float v0 = acc[mt][nt][rh * 2 + 0] * scl;
                float v1 = acc[mt][nt][rh * 2 + 1] * scl;
                if (isSkip) {
                    int c = cb_local + nt * 8 + tg * 2;
                    v0 += skb[c]; v1 += skb[c + 1];
                } else {
                    int c = cbase + nt * 8 + tg * 2;
                    float s0 = a_s[c], s1 = a_s[c + 1];
                    float d0 = a_d[c], d1 = a_d[c + 1];
                    if (nt < 4) {
                        ds0 = fmaf(v0, s0, fmaf(v1, s1, ds0));
                        dd0 = fmaf(v0, d0, fmaf(v1, d1, dd0));
                    } else {
                        ds1 = fmaf(v0, s0, fmaf(v1, s1, ds1));
                        dd1 = fmaf(v0, d0, fmaf(v1, d1, dd1));
                    }
                }
                v[nt][0] = v0; v[nt][1] = v1;
            }
            if (!isSkip) {
                ds0 += __shfl_xor_sync(0xffffffffu, ds0, 1);
                ds0 += __shfl_xor_sync(0xffffffffu, ds0, 2);
                dd0 += __shfl_xor_sync(0xffffffffu, dd0, 1);
                dd0 += __shfl_xor_sync(0xffffffffu, dd0, 2);
                ds1 += __shfl_xor_sync(0xffffffffu, ds1, 1);
                ds1 += __shfl_xor_sync(0xffffffffu, ds1, 2);
                dd1 += __shfl_xor_sync(0xffffffffu, dd1, 1);
                dd1 += __shfl_xor_sync(0xffffffffu, dd1, 2);
            }
            if (r < M) {
                if (isSkip) {
#pragma unroll
                    for (int nt = 0; nt < 8; nt++) {
                        int c = cb_local + nt * 8 + tg * 2;
                        *(float2*)(Cskip + (size_t)r * 128 + c) = make_float2(v[nt][0], v[nt][1]);
                    }
                } else {
#pragma unroll
                    for (int nt = 0; nt < 8; nt++) {
                        int c = cbase + nt * 8 + tg * 2;
                        __half2 p = __floats2half2_rn(v[nt][0], v[nt][1]);
                        hh[(size_t)r * halfN + (c >> 1)] = *(uint32_t*)&p;
                    }
                    if (tg == 0) {
                        int h0 = cbase >> 5;
                        asrc[(size_t)r * H + h0]     = ds0;
                        asrc[(size_t)r * H + h0 + 1] = ds1;
                        adst[(size_t)r * H + h0]     = dd0;
                        adst[(size_t)r * H + h0 + 1] = dd1;
                    }
                }
            }
        }
    }
}

// ---------------- GAT aggregation: warp per (node, half) for H=8; warp per node H=4 -------
template <int H, bool SL, bool BN, bool FINAL>
__global__ void k_agg(const uint32_t* __restrict__ hh, const float* __restrict__ bias,
                      uint16_t* __restrict__ outH, uint16_t* __restrict__ outL, int n,
                      const float* __restrict__ bg, const float* __restrict__ bb,
                      const float* __restrict__ bmean, const float* __restrict__ bvar,
                      const uint16_t* __restrict__ resH, const uint16_t* __restrict__ resL,
                      const float* __restrict__ xi, const float* __restrict__ fcW,
                      const float* __restrict__ fcb, float* __restrict__ fout) {
    constexpr int D = H * 32;
    constexpr int ROW = D / 2;                     // uint32 per feature row
    constexpr int SHIFT = (H == 8) ? 1 : 0;
    constexpr int PL = 4;                          // dims per lane (both cases)
    int gw = (blockIdx.x * blockDim.x + threadIdx.x) >> 5;
    int l = threadIdx.x & 31;
    int node = gw >> SHIFT;
    int half = (H == 8) ? (gw & 1) : 0;
    if (node >= n) return;

    int myhead = half * 4 + (l >> 3);
    int d0 = half * 128 + 4 * l;
    float ad = g_adst[node * H + myhead];
    int rs = g_rowptr[node], re = g_rowptr[node + 1];

    float den = 0.f;
    float acc[PL] = { 0.f, 0.f, 0.f, 0.f };

    auto gather = [&](int s, float ex) {
        uint2 u = *(const uint2*)(hh + (size_t)s * ROW + (d0 >> 1));
        float2 f0 = __half22float2(*(__half2*)&u.x);
        float2 f1 = __half22float2(*(__half2*)&u.y);
        acc[0] = fmaf(ex, f0.x, acc[0]); acc[1] = fmaf(ex, f0.y, acc[1]);
        acc[2] = fmaf(ex, f1.x, acc[2]); acc[3] = fmaf(ex, f1.y, acc[3]);
    };
    auto logit = [&](int s) {
        float t = g_asrc[s * H + myhead] + ad;
        t = (t > 0.f) ? t : 0.2f * t;
        return __expf(t);
    };

    if (SL) {
        float ex = logit(node);
        den += ex;
        gather(node, ex);
    }
    int j = rs;
    for (; j + 3 < re; j += 4) {
        int s0 = g_col[j], s1 = g_col[j + 1], s2 = g_col[j + 2], s3 = g_col[j + 3];
        float e0 = logit(s0);
        float e1 = logit(s1);
        float e2 = logit(s2);
        float e3 = logit(s3);
        den += (e0 + e1) + (e2 + e3);
        gather(s0, e0);
        gather(s1, e1);
        gather(s2, e2);
        gather(s3, e3);
    }
    for (; j < re; j++) {
        int s = g_col[j];
        float ex = logit(s);
        den += ex;
        gather(s, ex);
    }

    float inv = 1.f / (den + 1e-16f);
    float o[PL];
#pragma unroll
    for (int q = 0; q < PL; q++) o[q] = acc[q] * inv + bias[d0 + q];

    if (BN) {
        float rr[PL] = { 0.f, 0.f, 0.f, 0.f };
        if (resH) {
            uint2 uh = *(const uint2*)((const uint32_t*)resH + (size_t)node * 128 + (d0 >> 1));
            uint2 ul = *(const uint2*)((const uint32_t*)resL + (size_t)node * 128 + (d0 >> 1));
            rec_pair(uh.x, ul.x, rr[0], rr[1]);
            rec_pair(uh.y, ul.y, rr[2], rr[3]);
        }
        float4 gg = *(const float4*)(bg + d0);
        float4 bbv = *(const float4*)(bb + d0);
        float4 mm = *(const float4*)(bmean + d0);
        float4 vv = *(const float4*)(bvar + d0);
        float gx[4] = { gg.x, gg.y, gg.z, gg.w }, bx[4] = { bbv.x, bbv.y, bbv.z, bbv.w };
        float mx[4] = { mm.x, mm.y, mm.z, mm.w }, vx[4] = { vv.x, vv.y, vv.z, vv.w };
#pragma unroll
        for (int q = 0; q < 4; q++) {
            float val = (o[q] - mx[q]) * rsqrtf(vx[q] + 1e-5f) * gx[q] + bx[q] + rr[q];
            o[q] = (val > 0.f) ? val : expm1f(val);
        }
    }

    if (!FINAL) {
        uint32_t hw[2], lw[2];
        hw[0] = split_pair(o[0], o[1], lw[0]);
        hw[1] = split_pair(o[2], o[3], lw[1]);
        *(uint2*)((uint32_t*)outH + (size_t)node * 128 + (d0 >> 1)) = make_uint2(hw[0], hw[1]);
        *(uint2*)((uint32_t*)outL + (size_t)node * 128 + (d0 >> 1)) = make_uint2(lw[0], lw[1]);
    } else {
        float4 x4 = *(const float4*)(xi + (size_t)node * 128 + d0);
        float v[4] = { o[0] + x4.x, o[1] + x4.y, o[2] + x4.z, o[3] + x4.w };
        float z0 = 0.f, z1 = 0.f;
#pragma unroll
        for (int q = 0; q < 4; q++) {
            z0 = fmaf(v[q], fcW[(d0 + q) * 2], z0);
            z1 = fmaf(v[q], fcW[(d0 + q) * 2 + 1], z1);
        }
#pragma unroll
        for (int off = 16; off; off >>= 1) {
            z0 += __shfl_down_sync(0xffffffffu, z0, off);
            z1 += __shfl_down_sync(0xffffffffu, z1, off);
        }
        if (l == 0) {
            z0 += fcb[0]; z1 += fcb[1];
            float mx = fmaxf(z0, z1);
            float lse = mx + logf(expf(z0 - mx) + expf(z1 - mx));
            fout[node * 2] = z0 - lse;
            fout[node * 2 + 1] = z1 - lse;
        }
    }
}

// ---------------- launch ----------------
extern "C" void kernel_launch(void* const* d_in, const int* in_sizes, int n_in,
                              void* d_out, int out_size) {
    const float* x   = (const float*)d_in[0];
    const int*   ei  = (const int*)d_in[1];
    const float* W1  = (const float*)d_in[2];
    const float* a1s = (const float*)d_in[3];
    const float* a1d = (const float*)d_in[4];
    const float* b1  = (const float*)d_in[5];
    const float* g1  = (const float*)d_in[6];
    const float* be1 = (const float*)d_in[7];
    const float* m1  = (const float*)d_in[8];
    const float* v1  = (const float*)d_in[9];
    const float* W2  = (const float*)d_in[10];
    const float* a2s = (const float*)d_in[11];
    const float* a2d = (const float*)d_in[12];
    const float* b2  = (const float*)d_in[13];
    const float* g2  = (const float*)d_in[14];
    const float* be2 = (const float*)d_in[15];
    const float* m2  = (const float*)d_in[16];
    const float* v2  = (const float*)d_in[17];
    const float* W3  = (const float*)d_in[18];
    const float* a3s = (const float*)d_in[19];
    const float* a3d = (const float*)d_in[20];
    const float* b3  = (const float*)d_in[21];
    const float* fcW = (const float*)d_in[22];
    const float* fcb = (const float*)d_in[23];
    const float* skW = (const float*)d_in[24];
    const float* skb = (const float*)d_in[25];
    const float* temp = (const float*)d_in[26];

    int n = in_sizes[0] / FIN;   // 50000
    int e = in_sizes[1] / 2;     // 800000
    const int* src = ei;
    const int* dst = ei + e;

    float *xinit, *asrc, *adst;
    uint32_t* hh;
    uint16_t *xH, *xL, *p1H, *p1L, *p2H, *p2L;
    uint16_t *w1H, *w1L, *w2H, *w2L, *w3H, *w3L, *skH, *skL;
    cudaGetSymbolAddress((void**)&hh, g_hh);
    cudaGetSymbolAddress((void**)&xinit, g_xinit);
    cudaGetSymbolAddress((void**)&asrc, g_asrc);
    cudaGetSymbolAddress((void**)&adst, g_adst);
    cudaGetSymbolAddress((void**)&xH, g_xH);
    cudaGetSymbolAddress((void**)&xL, g_xL);
    cudaGetSymbolAddress((void**)&p1H, g_p1H);
    cudaGetSymbolAddress((void**)&p1L, g_p1L);
    cudaGetSymbolAddress((void**)&p2H, g_p2H);
    cudaGetSymbolAddress((void**)&p2L, g_p2L);
    cudaGetSymbolAddress((void**)&w1H, g_w1H);
    cudaGetSymbolAddress((void**)&w1L, g_w1L);
    cudaGetSymbolAddress((void**)&w2H, g_w2H);
    cudaGetSymbolAddress((void**)&w2L, g_w2L);
    cudaGetSymbolAddress((void**)&w3H, g_w3H);
    cudaGetSymbolAddress((void**)&w3L, g_w3L);
    cudaGetSymbolAddress((void**)&skH, g_skH);
    cudaGetSymbolAddress((void**)&skL, g_skL);

    // side stream + fork/join events (created once; no device allocation)
    static cudaStream_t s2 = nullptr;
    static cudaEvent_t evFork = nullptr, evJoin = nullptr;
    if (!s2) {
        cudaStreamCreateWithFlags(&s2, cudaStreamNonBlocking);
        cudaEventCreateWithFlags(&evFork, cudaEventDisableTiming);
        cudaEventCreateWithFlags(&evJoin, cudaEventDisableTiming);
    }

    int nb256 = (n + 255) / 256;
    int eb256 = (e + 255) / 256;
    int wg1 = (n * 32 + 255) / 256;     // 1 warp/node (H=4, final)
    int wg2 = (n * 64 + 255) / 256;     // 2 warps/node (H=8)
    int gm = (n + 127) / 128;

    // ---- fork: CSR build + W2/W3 splits on side stream ----
    cudaEventRecord(evFork, 0);
    cudaStreamWaitEvent(s2, evFork, 0);

    k_split_w<<<(256 * 128 + 255) / 256, 256, 0, s2>>>(W2, 256, 256, 256, w2H, w2L);
    k_split_w<<<(128 * 128 + 255) / 256, 256, 0, s2>>>(W3, 256, 128, 256, w3H, w3L);
    k_zero<<<nb256, 256, 0, s2>>>(n);
    k_count<<<eb256, 256, 0, s2>>>(dst, e);
    k_bsum<<<nb256, 256, 0, s2>>>(n);
    k_bscan<<<1, 256, 0, s2>>>(nb256, n);
    k_rowptr<<<nb256, 256, 0, s2>>>(n);
    k_scatter<<<eb256, 256, 0, s2>>>(src, dst, e);
    cudaEventRecord(evJoin, s2);

    // legacy stream: x/W1/skW splits + layer-1/skip GEMM (independent of CSR)
    k_split_x<<<(n * 88 + 255) / 256, 256>>>(x, n);
    k_split_w<<<(256 * 88 + 255) / 256, 256>>>(W1, FIN, 256, 176, w1H, w1L);
    k_split_w<<<(128 * 88 + 255) / 256, 256>>>(skW, FIN, 128, 176, skH, skL);

    k_pgemm<true><<<dim3(3, gm), 256>>>(xH, xL, 176, w1H, w1L, skH, skL,
                                        xinit, skb, hh, n, 256, nullptr,
                                        asrc, adst, a1s, a1d, 8);

    // ---- join: agg needs CSR; layer-2 GEMM needs W2 split ----
    cudaStreamWaitEvent(0, evJoin, 0);

    k_agg<8, false, true, false><<<wg2, 256>>>(hh, b1, p1H, p1L, n, g1, be1, m1, v1,
                                               nullptr, nullptr, nullptr, nullptr, nullptr, nullptr);

    // ---- layer 2 (self loops, residual from p1 planes) ----
    k_pgemm<false><<<dim3(2, gm), 256>>>(p1H, p1L, 256, w2H, w2L, nullptr, nullptr,
                                         nullptr, nullptr, hh, n, 256, nullptr,
                                         asrc, adst, a2s, a2d, 8);
    k_agg<8, true, true, false><<<wg2, 256>>>(hh, b2, p2H, p2L, n, g2, be2, m2, v2,
                                              p1H, p1L, nullptr, nullptr, nullptr, nullptr);

    // ---- layer 3 (self loops, temp folded into GEMM scale), fused final ----
    k_pgemm<false><<<dim3(1, gm), 256>>>(p2H, p2L, 256, w3H, w3L, nullptr, nullptr,
                                         nullptr, nullptr, hh, n, 128, temp,
                                         asrc, adst, a3s, a3d, 4);
    k_agg<4, true, false, true><<<wg1, 256>>>(hh, b3, nullptr, nullptr, n,
                                              nullptr, nullptr, nullptr, nullptr,
                                              nullptr, nullptr, xinit, fcW, fcb, (float*)d_out);
}

// round 17
// speedup vs baseline: 1.1124x; 1.1124x over previous
#include <cuda_runtime.h>
#include <cuda_fp16.h>
#include <cuda_bf16.h>
#include <math.h>
#include <cstdint>

#define NN 50000
#define EE 800000
#define FIN 165
#define MPAD 50048            // 391 * 128

// ---------------- scratch (device globals; no allocation allowed) ----------------
__device__ uint16_t g_xH[MPAD * 176], g_xL[MPAD * 176];
__device__ uint16_t g_p1H[MPAD * 256], g_p1L[MPAD * 256];
__device__ uint16_t g_p2H[MPAD * 256], g_p2L[MPAD * 256];
__device__ uint16_t g_w1H[256 * 176], g_w1L[256 * 176];
__device__ uint16_t g_w2H[256 * 256], g_w2L[256 * 256];
__device__ uint16_t g_w3H[128 * 256], g_w3L[128 * 256];
__device__ uint16_t g_skH[128 * 176], g_skL[128 * 176];
__device__ uint32_t g_hh[NN * 128];     // packed half2 features
__device__ float g_xinit[NN * 128];
__device__ float g_asrc[NN * 8];
__device__ float g_adst[NN * 8];
__device__ int   g_rowptr[NN + 1];
__device__ int   g_cursor[NN];
__device__ int   g_col[EE];
__device__ int   g_bsum[256];

// ---------------- split helpers ----------------
__device__ __forceinline__ uint32_t split_pair(float v0, float v1, uint32_t& loOut) {
    uint32_t b0 = __float_as_uint(v0), b1 = __float_as_uint(v1);
    float l0 = v0 - __uint_as_float(b0 & 0xFFFF0000u);
    float l1 = v1 - __uint_as_float(b1 & 0xFFFF0000u);
    __nv_bfloat162 lp = __floats2bfloat162_rn(l0, l1);
    loOut = *(uint32_t*)&lp;
    return (b0 >> 16) | (b1 & 0xFFFF0000u);
}
__device__ __forceinline__ void rec_pair(uint32_t h, uint32_t lo, float& r0, float& r1) {
    float h0 = __uint_as_float(h << 16);
    float h1 = __uint_as_float(h & 0xFFFF0000u);
    __nv_bfloat162 lp = *(__nv_bfloat162*)&lo;
    float2 lf = __bfloat1622float2(lp);
    r0 = h0 + lf.x; r1 = h1 + lf.y;
}

// ---------------- prep: split x + split/transpose weights ----------------
__global__ void k_split_x(const float* __restrict__ x, int n) {
    int idx = blockIdx.x * 256 + threadIdx.x;
    int row = idx / 88, cp = idx - row * 88;
    if (row >= n) return;
    int c0 = cp * 2;
    float v0 = (c0 < FIN) ? x[(size_t)row * FIN + c0] : 0.f;
    float v1 = (c0 + 1 < FIN) ? x[(size_t)row * FIN + c0 + 1] : 0.f;
    uint32_t lo, hi = split_pair(v0, v1, lo);
    ((uint32_t*)g_xH)[(size_t)row * 88 + cp] = hi;
    ((uint32_t*)g_xL)[(size_t)row * 88 + cp] = lo;
}
__global__ void k_split_w(const float* __restrict__ W, int K, int N, int Kp,
                          uint16_t* __restrict__ oH, uint16_t* __restrict__ oL) {
    int kp2 = Kp >> 1;
    int idx = blockIdx.x * 256 + threadIdx.x;
    if (idx >= N * kp2) return;
    int row = idx / kp2, cp = idx - row * kp2;
    int k0 = cp * 2;
    float v0 = (k0 < K) ? W[(size_t)k0 * N + row] : 0.f;
    float v1 = (k0 + 1 < K) ? W[(size_t)(k0 + 1) * N + row] : 0.f;
    uint32_t lo, hi = split_pair(v0, v1, lo);
    ((uint32_t*)oH)[(size_t)row * kp2 + cp] = hi;
    ((uint32_t*)oL)[(size_t)row * kp2 + cp] = lo;
}

// ---------------- CSR build (by destination), hierarchical scan ----------------
__global__ void k_zero(int n) {
    int i = blockIdx.x * blockDim.x + threadIdx.x;
    if (i < n) g_cursor[i] = 0;
}
__global__ void k_count(const int* __restrict__ dst, int e) {
    int i = blockIdx.x * blockDim.x + threadIdx.x;
    if (i < e) atomicAdd(&g_cursor[dst[i]], 1);
}
__global__ void k_bsum(int n) {
    __shared__ int sh[256];
    int i = blockIdx.x * 256 + threadIdx.x;
    sh[threadIdx.x] = (i < n) ? g_cursor[i] : 0;
    __syncthreads();
#pragma unroll
    for (int off = 128; off; off >>= 1) {
        if (threadIdx.x < off) sh[threadIdx.x] += sh[threadIdx.x + off];
        __syncthreads();
    }
    if (threadIdx.x == 0) g_bsum[blockIdx.x] = sh[0];
}
__global__ void k_bscan(int nb, int n) {
    __shared__ int sh[256];
    int t = threadIdx.x;
    int v = (t < nb) ? g_bsum[t] : 0;
    sh[t] = v;
    __syncthreads();
#pragma unroll
    for (int off = 1; off < 256; off <<= 1) {
        int u = (t >= off) ? sh[t - off] : 0;
        __syncthreads();
        sh[t] += u;
        __syncthreads();
    }
    if (t < nb) g_bsum[t] = sh[t] - v;
    if (t == 255) g_rowptr[n] = sh[255];
}
__global__ void k_rowptr(int n) {
    __shared__ int sh[256];
    int t = threadIdx.x;
    int i = blockIdx.x * 256 + t;
    int c = (i < n) ? g_cursor[i] : 0;
    sh[t] = c;
    __syncthreads();
#pragma unroll
    for (int off = 1; off < 256; off <<= 1) {
        int u = (t >= off) ? sh[t - off] : 0;
        __syncthreads();
        sh[t] += u;
        __syncthreads();
    }
    if (i < n) {
        int p = g_bsum[blockIdx.x] + sh[t] - c;
        g_rowptr[i] = p;
        g_cursor[i] = p;
    }
}
__global__ void k_scatter(const int* __restrict__ src, const int* __restrict__ dst, int e) {
    int i = blockIdx.x * blockDim.x + threadIdx.x;
    if (i >= e) return;
    int pos = atomicAdd(&g_cursor[dst[i]], 1);
    g_col[pos] = src[i];
}

// ---------------- mma / ldmatrix helpers ----------------
__device__ __forceinline__ void mma16816(float* c, const uint32_t* a, const uint32_t* b) {
    asm volatile(
        "mma.sync.aligned.m16n8k16.row.col.f32.bf16.bf16.f32 "
        "{%0,%1,%2,%3}, {%4,%5,%6,%7}, {%8,%9}, {%0,%1,%2,%3};"
        : "+f"(c[0]), "+f"(c[1]), "+f"(c[2]), "+f"(c[3])
        : "r"(a[0]), "r"(a[1]), "r"(a[2]), "r"(a[3]), "r"(b[0]), "r"(b[1]));
}
__device__ __forceinline__ void ldsm4(uint32_t* r, uint32_t addr) {
    asm volatile("ldmatrix.sync.aligned.m8n8.x4.shared.b16 {%0,%1,%2,%3}, [%4];"
                 : "=r"(r[0]), "=r"(r[1]), "=r"(r[2]), "=r"(r[3]) : "r"(addr));
}
__device__ __forceinline__ uint32_t smem_u32(const void* p) {
    uint32_t a;
    asm("{ .reg .u64 t; cvta.to.shared.u64 t, %1; cvt.u32.u64 %0, t; }" : "=r"(a) : "l"(p));
    return a;
}

#define LDSB 24   // bf16 per smem row (48B stride: 16B-aligned, conflict-free)

// ================= plane-fed bf16x3 tensor GEMM, 128x128 block, BK=16 =====================
template <bool FUSE_SKIP>
__global__ void __launch_bounds__(256, 2)
k_pgemm(const uint16_t* __restrict__ AH, const uint16_t* __restrict__ AL, int Kp,
        const uint16_t* __restrict__ BH, const uint16_t* __restrict__ BL,
        const uint16_t* __restrict__ SH_, const uint16_t* __restrict__ SL_,
        float* __restrict__ Cskip, const float* __restrict__ skb,
        uint32_t* __restrict__ hh, int M, int N,
        const float* __restrict__ scale,
        float* __restrict__ asrc, float* __restrict__ adst,
        const float* __restrict__ a_s, const float* __restrict__ a_d, int H) {
    __shared__ __align__(16) uint16_t AsH[2][128][LDSB];
    __shared__ __align__(16) uint16_t AsL[2][128][LDSB];
    __shared__ __align__(16) uint16_t BsH[2][128][LDSB];
    __shared__ __align__(16) uint16_t BsL[2][128][LDSB];

    int tid = threadIdx.x;
    int wid = tid >> 5;
    int lane = tid & 31;
    int g = lane >> 2, tg = lane & 3;
    int warp_m = wid & 3;
    int warp_n = wid >> 2;
    int bm = blockIdx.y * 128;

    const bool isSkip = FUSE_SKIP && (blockIdx.x == 0);
    int bn = FUSE_SKIP ? ((int)blockIdx.x - 1) * 128 : (int)blockIdx.x * 128;
    const uint16_t* pBH = isSkip ? SH_ : BH;
    const uint16_t* pBL = isSkip ? SL_ : BL;

    int r2 = tid >> 1, hf = tid & 1;
    size_t aoff = (size_t)(bm + r2) * Kp + hf * 8;
    size_t boff = (size_t)((isSkip ? 0 : bn) + r2) * Kp + hf * 8;

    float acc[2][8][4];
#pragma unroll
    for (int mt = 0; mt < 2; mt++)
#pragma unroll
        for (int nt = 0; nt < 8; nt++)
#pragma unroll
            for (int q = 0; q < 4; q++) acc[mt][nt][q] = 0.f;

    int lr = lane & 7, sel = lane >> 3;
    uint32_t aRow = (uint32_t)(warp_m * 32 + lr + ((sel & 1) << 3));
    uint32_t aColB = (uint32_t)(((sel >> 1) << 3) * 2);
    uint32_t bRow = (uint32_t)(warp_n * 64 + lr + ((sel >> 1) << 3));
    uint32_t bColB = (uint32_t)(((sel & 1) << 3) * 2);

    uint32_t sAH = smem_u32(&AsH[0][0][0]);
    uint32_t sAL = smem_u32(&AsL[0][0][0]);
    uint32_t sBH = smem_u32(&BsH[0][0][0]);
    uint32_t sBL = smem_u32(&BsL[0][0][0]);
    const uint32_t BUF = 128 * LDSB * 2;

    uint4 avh, avl, bvh, bvl;
    int nk = Kp >> 4;

#define LOADG(k0)                                              \
    {                                                          \
        avh = *(const uint4*)(AH + aoff + (k0));               \
        avl = *(const uint4*)(AL + aoff + (k0));               \
        bvh = *(const uint4*)(pBH + boff + (k0));              \
        bvl = *(const uint4*)(pBL + boff + (k0));              \
    }
#define STORES(buf)                                            \
    {                                                          \
        *(uint4*)&AsH[buf][r2][hf * 8] = avh;                  \
        *(uint4*)&AsL[buf][r2][hf * 8] = avl;                  \
        *(uint4*)&BsH[buf][r2][hf * 8] = bvh;                  \
        *(uint4*)&BsL[buf][r2][hf * 8] = bvl;                  \
    }

    LOADG(0);
    STORES(0);
    __syncthreads();

    for (int t = 0; t < nk; t++) {
        int cur = t & 1;
        uint32_t base = cur * BUF;
        if (t + 1 < nk) LOADG((t + 1) << 4);

        uint32_t aH2[2][4], aL2[2][4];
#pragma unroll
        for (int mt = 0; mt < 2; mt++) {
            uint32_t off = (aRow + mt * 16) * (LDSB * 2) + aColB;
            ldsm4(aH2[mt], sAH + base + off);
            ldsm4(aL2[mt], sAL + base + off);
        }
#pragma unroll
        for (int ntp = 0; ntp < 4; ntp++) {
            uint32_t off = (bRow + ntp * 16) * (LDSB * 2) + bColB;
            uint32_t bh[4], bl[4];
            ldsm4(bh, sBH + base + off);
            ldsm4(bl, sBL + base + off);
#pragma unroll
            for (int mt = 0; mt < 2; mt++) {
                mma16816(acc[mt][2 * ntp],     aH2[mt], bh);
                mma16816(acc[mt][2 * ntp],     aH2[mt], bl);
                mma16816(acc[mt][2 * ntp],     aL2[mt], bh);
                mma16816(acc[mt][2 * ntp + 1], aH2[mt], bh + 2);
                mma16816(acc[mt][2 * ntp + 1], aH2[mt], bl + 2);
                mma16816(acc[mt][2 * ntp + 1], aL2[mt], bh + 2);
            }
        }
        if (t + 1 < nk) {
            STORES(cur ^ 1);
            __syncthreads();
        }
    }
#undef LOADG
#undef STORES

    // ---- epilogue ----
    float scl = scale ? *scale : 1.0f;
    int cb_local = warp_n * 64;
    int cbase = bn + cb_local;
    int halfN = N >> 1;
#pragma unroll
    for (int mt = 0; mt < 2; mt++) {
#pragma unroll
        for (int rh = 0; rh < 2; rh++) {
            int r = bm + warp_m * 32 + mt * 16 + rh * 8 + g;
            float v[8][2];
            float ds0 = 0.f, dd0 = 0.f, ds1 = 0.f, dd1 = 0.f;
#pragma unroll
            for (int nt = 0; nt < 8; nt++) {
                float v0 = acc[mt][nt][rh * 2 + 0] * scl;
                float v1 = acc[mt][nt][rh * 2 + 1] * scl;
                if (isSkip) {
                    int c = cb_local + nt * 8 + tg * 2;
                    v0 += skb[c]; v1 += skb[c + 1];
                } else {
                    int c = cbase + nt * 8 + tg * 2;
                    float s0 = a_s[c], s1 = a_s[c + 1];
                    float d0 = a_d[c], d1 = a_d[c + 1];
                    if (nt < 4) {
                        ds0 = fmaf(v0, s0, fmaf(v1, s1, ds0));
                        dd0 = fmaf(v0, d0, fmaf(v1, d1, dd0));
                    } else {
                        ds1 = fmaf(v0, s0, fmaf(v1, s1, ds1));
                        dd1 = fmaf(v0, d0, fmaf(v1, d1, dd1));
                    }
                }
                v[nt][0] = v0; v[nt][1] = v1;
            }
            if (!isSkip) {
                ds0 += __shfl_xor_sync(0xffffffffu, ds0, 1);
                ds0 += __shfl_xor_sync(0xffffffffu, ds0, 2);
                dd0 += __shfl_xor_sync(0xffffffffu, dd0, 1);
                dd0 += __shfl_xor_sync(0xffffffffu, dd0, 2);
                ds1 += __shfl_xor_sync(0xffffffffu, ds1, 1);
                ds1 += __shfl_xor_sync(0xffffffffu, ds1, 2);
                dd1 += __shfl_xor_sync(0xffffffffu, dd1, 1);
                dd1 += __shfl_xor_sync(0xffffffffu, dd1, 2);
            }
            if (r < M) {
                if (isSkip) {
#pragma unroll
                    for (int nt = 0; nt < 8; nt++) {
                        int c = cb_local + nt * 8 + tg * 2;
                        *(float2*)(Cskip + (size_t)r * 128 + c) = make_float2(v[nt][0], v[nt][1]);
                    }
                } else {
#pragma unroll
                    for (int nt = 0; nt < 8; nt++) {
                        int c = cbase + nt * 8 + tg * 2;
                        __half2 p = __floats2half2_rn(v[nt][0], v[nt][1]);
                        hh[(size_t)r * halfN + (c >> 1)] = *(uint32_t*)&p;
                    }
                    if (tg == 0) {
                        int h0 = cbase >> 5;
                        asrc[(size_t)r * H + h0]     = ds0;
                        asrc[(size_t)r * H + h0 + 1] = ds1;
                        adst[(size_t)r * H + h0]     = dd0;
                        adst[(size_t)r * H + h0 + 1] = dd1;
                    }
                }
            }
        }
    }
}

// ---------------- GAT aggregation, one warp per node; outputs bf16 planes -----------------
template <int H, bool SL, bool BN, bool FINAL>
__global__ void k_agg(const uint32_t* __restrict__ hh, const float* __restrict__ bias,
                      uint16_t* __restrict__ outH, uint16_t* __restrict__ outL, int n,
                      const float* __restrict__ bg, const float* __restrict__ bb,
                      const float* __restrict__ bmean, const float* __restrict__ bvar,
                      const uint16_t* __restrict__ resH, const uint16_t* __restrict__ resL,
                      const float* __restrict__ xi, const float* __restrict__ fcW,
                      const float* __restrict__ fcb, float* __restrict__ fout) {
    constexpr int D = H * 32;
    constexpr int ROW = D / 2;
    constexpr int PL = (H == 8) ? 8 : 4;
    int node = (blockIdx.x * blockDim.x + threadIdx.x) >> 5;
    int l = threadIdx.x & 31;
    if (node >= n) return;

    int myhead = (H == 8) ? (l >> 2) : (l >> 3);
    int d0 = PL * l;
    float ad = g_adst[node * H + myhead];
    int rs = g_rowptr[node], re = g_rowptr[node + 1];

    float den = 0.f;
    float acc[PL];
#pragma unroll
    for (int q = 0; q < PL; q++) acc[q] = 0.f;

    auto gather = [&](int s, float ex) {
        if (H == 8) {
            uint4 u = *(const uint4*)(hh + (size_t)s * ROW + (d0 >> 1));
            float2 f0 = __half22float2(*(__half2*)&u.x);
            float2 f1 = __half22float2(*(__half2*)&u.y);
            float2 f2 = __half22float2(*(__half2*)&u.z);
            float2 f3 = __half22float2(*(__half2*)&u.w);
            acc[0] = fmaf(ex, f0.x, acc[0]); acc[1] = fmaf(ex, f0.y, acc[1]);
            acc[2] = fmaf(ex, f1.x, acc[2]); acc[3] = fmaf(ex, f1.y, acc[3]);
            acc[4] = fmaf(ex, f2.x, acc[4]); acc[5] = fmaf(ex, f2.y, acc[5]);
            acc[6] = fmaf(ex, f3.x, acc[6]); acc[7] = fmaf(ex, f3.y, acc[7]);
        } else {
            uint2 u = *(const uint2*)(hh + (size_t)s * ROW + (d0 >> 1));
            float2 f0 = __half22float2(*(__half2*)&u.x);
            float2 f1 = __half22float2(*(__half2*)&u.y);
            acc[0] = fmaf(ex, f0.x, acc[0]); acc[1] = fmaf(ex, f0.y, acc[1]);
            acc[2] = fmaf(ex, f1.x, acc[2]); acc[3] = fmaf(ex, f1.y, acc[3]);
        }
    };
    auto logit = [&](int s) {
        float t = g_asrc[s * H + myhead] + ad;
        t = (t > 0.f) ? t : 0.2f * t;
        return __expf(t);
    };

    if (SL) {
        float ex = logit(node);
        den += ex;
        gather(node, ex);
    }
    int j = rs;
    for (; j + 3 < re; j += 4) {
        int s0 = g_col[j], s1 = g_col[j + 1], s2 = g_col[j + 2], s3 = g_col[j + 3];
        float e0 = logit(s0);
        float e1 = logit(s1);
        float e2 = logit(s2);
        float e3 = logit(s3);
        den += (e0 + e1) + (e2 + e3);
        gather(s0, e0);
        gather(s1, e1);
        gather(s2, e2);
        gather(s3, e3);
    }
    for (; j < re; j++) {
        int s = g_col[j];
        float ex = logit(s);
        den += ex;
        gather(s, ex);
    }

    float inv = 1.f / (den + 1e-16f);
    float o[PL];
#pragma unroll
    for (int q = 0; q < PL; q++) o[q] = acc[q] * inv + bias[d0 + q];

    if (BN) {
        float rr[PL];
#pragma unroll
        for (int q = 0; q < PL; q++) rr[q] = 0.f;
        if (resH) {
            uint4 uh = *(const uint4*)((const uint32_t*)resH + (size_t)node * 128 + 4 * l);
            uint4 ul = *(const uint4*)((const uint32_t*)resL + (size_t)node * 128 + 4 * l);
            rec_pair(uh.x, ul.x, rr[0], rr[1]);
            rec_pair(uh.y, ul.y, rr[2], rr[3]);
            rec_pair(uh.z, ul.z, rr[4], rr[5]);
            rec_pair(uh.w, ul.w, rr[6], rr[7]);
        }
#pragma unroll
        for (int q = 0; q < PL; q += 4) {
            float4 gg = *(const float4*)(bg + d0 + q);
            float4 bbv = *(const float4*)(bb + d0 + q);
            float4 mm = *(const float4*)(bmean + d0 + q);
            float4 vv = *(const float4*)(bvar + d0 + q);
            float gx[4] = { gg.x, gg.y, gg.z, gg.w }, bx[4] = { bbv.x, bbv.y, bbv.z, bbv.w };
            float mx[4] = { mm.x, mm.y, mm.z, mm.w }, vx[4] = { vv.x, vv.y, vv.z, vv.w };
#pragma unroll
            for (int q2 = 0; q2 < 4; q2++) {
                float val = (o[q + q2] - mx[q2]) * rsqrtf(vx[q2] + 1e-5f) * gx[q2] + bx[q2] + rr[q + q2];
                o[q + q2] = (val > 0.f) ? val : expm1f(val);
            }
        }
    }

    if (!FINAL) {
        uint32_t hw[4], lw[4];
#pragma unroll
        for (int qq = 0; qq < 4; qq++) hw[qq] = split_pair(o[2 * qq], o[2 * qq + 1], lw[qq]);
        *(uint4*)((uint32_t*)outH + (size_t)node * 128 + 4 * l) = make_uint4(hw[0], hw[1], hw[2], hw[3]);
        *(uint4*)((uint32_t*)outL + (size_t)node * 128 + 4 * l) = make_uint4(lw[0], lw[1], lw[2], lw[3]);
    } else {
        float4 x4 = *(const float4*)(xi + (size_t)node * 128 + d0);
        float v[4] = { o[0] + x4.x, o[1] + x4.y, o[2] + x4.z, o[3] + x4.w };
        float z0 = 0.f, z1 = 0.f;
#pragma unroll
        for (int q = 0; q < 4; q++) {
            z0 = fmaf(v[q], fcW[(d0 + q) * 2], z0);
            z1 = fmaf(v[q], fcW[(d0 + q) * 2 + 1], z1);
        }
#pragma unroll
        for (int off = 16; off; off >>= 1) {
            z0 += __shfl_down_sync(0xffffffffu, z0, off);
            z1 += __shfl_down_sync(0xffffffffu, z1, off);
        }
        if (l == 0) {
            z0 += fcb[0]; z1 += fcb[1];
            float mx = fmaxf(z0, z1);
            float lse = mx + logf(expf(z0 - mx) + expf(z1 - mx));
            fout[node * 2] = z0 - lse;
            fout[node * 2 + 1] = z1 - lse;
        }
    }
}

// ---------------- launch ----------------
extern "C" void kernel_launch(void* const* d_in, const int* in_sizes, int n_in,
                              void* d_out, int out_size) {
    const float* x   = (const float*)d_in[0];
    const int*   ei  = (const int*)d_in[1];
    const float* W1  = (const float*)d_in[2];
    const float* a1s = (const float*)d_in[3];
    const float* a1d = (const float*)d_in[4];
    const float* b1  = (const float*)d_in[5];
    const float* g1  = (const float*)d_in[6];
    const float* be1 = (const float*)d_in[7];
    const float* m1  = (const float*)d_in[8];
    const float* v1  = (const float*)d_in[9];
    const float* W2  = (const float*)d_in[10];
    const float* a2s = (const float*)d_in[11];
    const float* a2d = (const float*)d_in[12];
    const float* b2  = (const float*)d_in[13];
    const float* g2  = (const float*)d_in[14];
    const float* be2 = (const float*)d_in[15];
    const float* m2  = (const float*)d_in[16];
    const float* v2  = (const float*)d_in[17];
    const float* W3  = (const float*)d_in[18];
    const float* a3s = (const float*)d_in[19];
    const float* a3d = (const float*)d_in[20];
    const float* b3  = (const float*)d_in[21];
    const float* fcW = (const float*)d_in[22];
    const float* fcb = (const float*)d_in[23];
    const float* skW = (const float*)d_in[24];
    const float* skb = (const float*)d_in[25];
    const float* temp = (const float*)d_in[26];

    int n = in_sizes[0] / FIN;   // 50000
    int e = in_sizes[1] / 2;     // 800000
    const int* src = ei;
    const int* dst = ei + e;

    float *xinit, *asrc, *adst;
    uint32_t* hh;
    uint16_t *xH, *xL, *p1H, *p1L, *p2H, *p2L;
    uint16_t *w1H, *w1L, *w2H, *w2L, *w3H, *w3L, *skH, *skL;
    cudaGetSymbolAddress((void**)&hh, g_hh);
    cudaGetSymbolAddress((void**)&xinit, g_xinit);
    cudaGetSymbolAddress((void**)&asrc, g_asrc);
    cudaGetSymbolAddress((void**)&adst, g_adst);
    cudaGetSymbolAddress((void**)&xH, g_xH);
    cudaGetSymbolAddress((void**)&xL, g_xL);
    cudaGetSymbolAddress((void**)&p1H, g_p1H);
    cudaGetSymbolAddress((void**)&p1L, g_p1L);
    cudaGetSymbolAddress((void**)&p2H, g_p2H);
    cudaGetSymbolAddress((void**)&p2L, g_p2L);
    cudaGetSymbolAddress((void**)&w1H, g_w1H);
    cudaGetSymbolAddress((void**)&w1L, g_w1L);
    cudaGetSymbolAddress((void**)&w2H, g_w2H);
    cudaGetSymbolAddress((void**)&w2L, g_w2L);
    cudaGetSymbolAddress((void**)&w3H, g_w3H);
    cudaGetSymbolAddress((void**)&w3L, g_w3L);
    cudaGetSymbolAddress((void**)&skH, g_skH);
    cudaGetSymbolAddress((void**)&skL, g_skL);

    // side stream + fork/join events (created once; no device allocation)
    static cudaStream_t s2 = nullptr;
    static cudaEvent_t evFork = nullptr, evJoin = nullptr;
    if (!s2) {
        cudaStreamCreateWithFlags(&s2, cudaStreamNonBlocking);
        cudaEventCreateWithFlags(&evFork, cudaEventDisableTiming);
        cudaEventCreateWithFlags(&evJoin, cudaEventDisableTiming);
    }

    int nb256 = (n + 255) / 256;
    int eb256 = (e + 255) / 256;
    int wg1 = (n * 32 + 255) / 256;
    int gm = (n + 127) / 128;

    // ---- fork: CSR build + W2/W3 splits on side stream ----
    cudaEventRecord(evFork, 0);
    cudaStreamWaitEvent(s2, evFork, 0);

    k_split_w<<<(256 * 128 + 255) / 256, 256, 0, s2>>>(W2, 256, 256, 256, w2H, w2L);
    k_split_w<<<(128 * 128 + 255) / 256, 256, 0, s2>>>(W3, 256, 128, 256, w3H, w3L);
    k_zero<<<nb256, 256, 0, s2>>>(n);
    k_count<<<eb256, 256, 0, s2>>>(dst, e);
    k_bsum<<<nb256, 256, 0, s2>>>(n);
    k_bscan<<<1, 256, 0, s2>>>(nb256, n);
    k_rowptr<<<nb256, 256, 0, s2>>>(n);
    k_scatter<<<eb256, 256, 0, s2>>>(src, dst, e);
    cudaEventRecord(evJoin, s2);

    // legacy stream: x/W1/skW splits + layer-1/skip GEMM (independent of CSR)
    k_split_x<<<(n * 88 + 255) / 256, 256>>>(x, n);
    k_split_w<<<(256 * 88 + 255) / 256, 256>>>(W1, FIN, 256, 176, w1H, w1L);
    k_split_w<<<(128 * 88 + 255) / 256, 256>>>(skW, FIN, 128, 176, skH, skL);

    k_pgemm<true><<<dim3(3, gm), 256>>>(xH, xL, 176, w1H, w1L, skH, skL,
                                        xinit, skb, hh, n, 256, nullptr,
                                        asrc, adst, a1s, a1d, 8);

    // ---- join: agg needs CSR; layer-2 GEMM needs W2 split ----
    cudaStreamWaitEvent(0, evJoin, 0);

    k_agg<8, false, true, false><<<wg1, 256>>>(hh, b1, p1H, p1L, n, g1, be1, m1, v1,
                                               nullptr, nullptr, nullptr, nullptr, nullptr, nullptr);

    // ---- layer 2 (self loops, residual from p1 planes) ----
    k_pgemm<false><<<dim3(2, gm), 256>>>(p1H, p1L, 256, w2H, w2L, nullptr, nullptr,
                                         nullptr, nullptr, hh, n, 256, nullptr,
                                         asrc, adst, a2s, a2d, 8);
    k_agg<8, true, true, false><<<wg1, 256>>>(hh, b2, p2H, p2L, n, g2, be2, m2, v2,
                                              p1H, p1L, nullptr, nullptr, nullptr, nullptr);

    // ---- layer 3 (self loops, temp folded into GEMM scale), fused final ----
    k_pgemm<false><<<dim3(1, gm), 256>>>(p2H, p2L, 256, w3H, w3L, nullptr, nullptr,
                                         nullptr, nullptr, hh, n, 128, temp,
                                         asrc, adst, a3s, a3d, 4);
    k_agg<4, true, false, true><<<wg1, 256>>>(hh, b3, nullptr, nullptr, n,
                                              nullptr, nullptr, nullptr, nullptr,
                                              nullptr, nullptr, xinit, fcW, fcb, (float*)d_out);
}